// round 1
// baseline (speedup 1.0000x reference)
#include <cuda_runtime.h>

// ---------------------------------------------------------------------------
// MOCA_80075370266907 — fp32 baseline, restructured as GEMM chain.
//
//   P = X @ [theta_w|phi_w|g_w]^T + bias          (8192 x 3072)
//   S1[b] = x[b] @ x[b]^T                          (4 x 2048 x 2048)
//   S2[b] = phi[b] @ theta[b]^T
//   moca[b] = softmax(r0*softmax(rowA)+r1*softmax(rowB)+rb)
//       with (rowA,rowB) = quirky cat/reshape pairing:
//       b=0:(S1_0,S1_1) b=1:(S1_2,S1_3) b=2:(S2_0,S2_1) b=3:(S2_2,S2_3)
//   Y[b][s,h] = sum_t moca[b][t,s] * g[b][t,h]     (TN gemm)
//   out = Y @ F^T + X @ emb_w^T + c,  F = emb_w @ w_w, c = emb_w@w_b + emb_b
// ---------------------------------------------------------------------------

namespace {
constexpr int CIN  = 2048;
constexpr int CHID = 1024;
constexpr int CEMB = 256;
constexpr int NB   = 4;
constexpr int TSQ  = 2048;
constexpr int NKS  = 16;   // split-K chunks for the tiny F gemm
}

// scratch (static device allocations — no dynamic alloc anywhere)
__device__ float d_Fp[(size_t)NKS * CEMB * CHID];
__device__ float d_F [(size_t)CEMB * CHID];
__device__ float d_c [CEMB];
__device__ float d_P [(size_t)NB * TSQ * 3 * CHID];   // [theta | phi | g] per (b,t)
__device__ float d_S1[(size_t)NB * TSQ * TSQ];
__device__ float d_S2[(size_t)NB * TSQ * TSQ];
__device__ float d_Mo[(size_t)NB * TSQ * TSQ];
__device__ float d_Yb[(size_t)NB * TSQ * CHID];

// ---------------------------------------------------------------------------
// Generic 128x128x8 SGEMM, 256 threads, 8x8 register tile per thread.
//   AKM=false: A is MxK row-major; AKM=true: A is KxM row-major
//   BKN=false: B is NxK row-major (NT); BKN=true: B is KxN row-major
//   SPLITK: blockIdx.z selects K chunk, C offset by z*sC (partials buffer)
// All M,N multiples of 128; K multiples of 8 (guaranteed by problem shapes).
// ---------------------------------------------------------------------------
template<bool AKM, bool BKN, bool BIAS, bool ACCUM, bool SPLITK>
__global__ __launch_bounds__(256, 2)
void gemm128(const float* __restrict__ Ag, const float* __restrict__ Bg,
             float* __restrict__ Cg, const float* __restrict__ bias,
             int M, int N, int K, int lda, int ldb, int ldc,
             long sA, long sB, long sC, int ksplit)
{
    __shared__ float As[8][132];
    __shared__ float Bs[8][132];
    const float* A = Ag;
    const float* B = Bg;
    float* C = Cg;
    int kbeg = 0, kend = K;
    if (SPLITK) {
        kbeg = blockIdx.z * ksplit;
        kend = kbeg + ksplit; if (kend > K) kend = K;
        C += (long)blockIdx.z * sC;
    } else {
        A += (long)blockIdx.z * sA;
        B += (long)blockIdx.z * sB;
        C += (long)blockIdx.z * sC;
    }
    const int m0 = blockIdx.y * 128, n0 = blockIdx.x * 128;
    const int tid = threadIdx.x;
    const int tx = tid & 15, ty = tid >> 4;
    const int aRow = tid >> 1, aK4 = (tid & 1) * 4;   // MK / NK loader
    const int aKr  = tid >> 5, aCol = (tid & 31) * 4; // KM / KN loader

    float acc[8][8];
    #pragma unroll
    for (int i = 0; i < 8; i++)
        #pragma unroll
        for (int j = 0; j < 8; j++) acc[i][j] = 0.f;

    for (int kk = kbeg; kk < kend; kk += 8) {
        __syncthreads();
        if (!AKM) {
            float4 v = *(const float4*)&A[(long)(m0 + aRow) * lda + kk + aK4];
            As[aK4+0][aRow] = v.x; As[aK4+1][aRow] = v.y;
            As[aK4+2][aRow] = v.z; As[aK4+3][aRow] = v.w;
        } else {
            float4 v = *(const float4*)&A[(long)(kk + aKr) * lda + m0 + aCol];
            *(float4*)&As[aKr][aCol] = v;
        }
        if (!BKN) {
            float4 v = *(const float4*)&B[(long)(n0 + aRow) * ldb + kk + aK4];
            Bs[aK4+0][aRow] = v.x; Bs[aK4+1][aRow] = v.y;
            Bs[aK4+2][aRow] = v.z; Bs[aK4+3][aRow] = v.w;
        } else {
            float4 v = *(const float4*)&B[(long)(kk + aKr) * ldb + n0 + aCol];
            *(float4*)&Bs[aKr][aCol] = v;
        }
        __syncthreads();
        #pragma unroll
        for (int k = 0; k < 8; k++) {
            float a[8], b[8];
            *(float4*)(a)     = *(const float4*)&As[k][ty * 4];
            *(float4*)(a + 4) = *(const float4*)&As[k][64 + ty * 4];
            *(float4*)(b)     = *(const float4*)&Bs[k][tx * 4];
            *(float4*)(b + 4) = *(const float4*)&Bs[k][64 + tx * 4];
            #pragma unroll
            for (int i = 0; i < 8; i++)
                #pragma unroll
                for (int j = 0; j < 8; j++)
                    acc[i][j] = fmaf(a[i], b[j], acc[i][j]);
        }
    }

    #pragma unroll
    for (int i = 0; i < 8; i++) {
        int m = m0 + ((i < 4) ? (ty * 4 + i) : (64 + ty * 4 + i - 4));
        #pragma unroll
        for (int h = 0; h < 2; h++) {
            int n = n0 + h * 64 + tx * 4;
            float4 v;
            v.x = acc[i][h*4+0]; v.y = acc[i][h*4+1];
            v.z = acc[i][h*4+2]; v.w = acc[i][h*4+3];
            long off = (long)m * ldc + n;
            if (BIAS) {
                v.x += bias[n+0]; v.y += bias[n+1];
                v.z += bias[n+2]; v.w += bias[n+3];
            }
            if (ACCUM) {
                float4 o = *(const float4*)&C[off];
                v.x += o.x; v.y += o.y; v.z += o.z; v.w += o.w;
            }
            *(float4*)&C[off] = v;
        }
    }
}

// deterministic reduce of split-K partials for F
__global__ void reduceF_kernel(const float* __restrict__ Fp, float* __restrict__ F)
{
    int i = blockIdx.x * 256 + threadIdx.x;
    float s = 0.f;
    #pragma unroll
    for (int z = 0; z < NKS; z++) s += Fp[(long)z * CEMB * CHID + i];
    F[i] = s;
}

// c[e] = dot(w_b, emb_w[e,:]) + emb_b[e]
__global__ void cvec_kernel(const float* __restrict__ emb_w,
                            const float* __restrict__ w_b,
                            const float* __restrict__ emb_b,
                            float* __restrict__ c)
{
    __shared__ float red[8];
    int e = blockIdx.x;
    float s = 0.f;
    for (int o = threadIdx.x; o < CIN; o += 256)
        s += w_b[o] * emb_w[(long)e * CIN + o];
    #pragma unroll
    for (int off = 16; off; off >>= 1) s += __shfl_xor_sync(0xffffffffu, s, off);
    if ((threadIdx.x & 31) == 0) red[threadIdx.x >> 5] = s;
    __syncthreads();
    if (threadIdx.x == 0) {
        float t = 0.f;
        #pragma unroll
        for (int w = 0; w < 8; w++) t += red[w];
        c[e] = t + emb_b[e];
    }
}

__device__ __forceinline__ float warpRed(float v, bool mx)
{
    #pragma unroll
    for (int o = 16; o; o >>= 1) {
        float w = __shfl_xor_sync(0xffffffffu, v, o);
        v = mx ? fmaxf(v, w) : v + w;
    }
    return v;
}

// one block per output row (b,t): softmax(rowA), softmax(rowB),
// L = r0*pA + r1*pB + rb, softmax(L)  -> moca row
__global__ void moca_kernel(const float* __restrict__ S1,
                            const float* __restrict__ S2,
                            float* __restrict__ Mo,
                            const float* __restrict__ rou_w,
                            const float* __restrict__ rou_b)
{
    __shared__ float red[8];
    const int row = blockIdx.x;                 // b*TSQ + t
    const int b = row >> 11, t = row & (TSQ - 1);
    const float* buf = (b < 2) ? S1 : S2;
    const int ba = (b & 1) * 2;                 // cat(axis=0).reshape quirk
    const float* rA = buf + ((long)ba * TSQ + t) * TSQ;
    const float* rB = buf + ((long)(ba + 1) * TSQ + t) * TSQ;
    const int tid = threadIdx.x;

    float v1[8], v2[8];
    #pragma unroll
    for (int q = 0; q < 8; q++) {
        v1[q] = rA[tid + 256 * q];
        v2[q] = rB[tid + 256 * q];
    }

    auto bred = [&](float v, bool mx) -> float {
        v = warpRed(v, mx);
        __syncthreads();
        if ((tid & 31) == 0) red[tid >> 5] = v;
        __syncthreads();
        float r = red[0];
        #pragma unroll
        for (int w = 1; w < 8; w++) r = mx ? fmaxf(r, red[w]) : r + red[w];
        return r;
    };

    float m = -3.4e38f;
    #pragma unroll
    for (int q = 0; q < 8; q++) m = fmaxf(m, v1[q]);
    m = bred(m, true);
    float s = 0.f;
    #pragma unroll
    for (int q = 0; q < 8; q++) { v1[q] = __expf(v1[q] - m); s += v1[q]; }
    const float inv1 = 1.f / bred(s, false);

    m = -3.4e38f;
    #pragma unroll
    for (int q = 0; q < 8; q++) m = fmaxf(m, v2[q]);
    m = bred(m, true);
    s = 0.f;
    #pragma unroll
    for (int q = 0; q < 8; q++) { v2[q] = __expf(v2[q] - m); s += v2[q]; }
    const float inv2 = 1.f / bred(s, false);

    const float r0 = rou_w[0], r1 = rou_w[1], rb = rou_b[0];
    #pragma unroll
    for (int q = 0; q < 8; q++)
        v1[q] = r0 * v1[q] * inv1 + r1 * v2[q] * inv2 + rb;

    m = -3.4e38f;
    #pragma unroll
    for (int q = 0; q < 8; q++) m = fmaxf(m, v1[q]);
    m = bred(m, true);
    s = 0.f;
    #pragma unroll
    for (int q = 0; q < 8; q++) { v1[q] = __expf(v1[q] - m); s += v1[q]; }
    const float invs = 1.f / bred(s, false);

    float* mo = Mo + (long)row * TSQ;
    #pragma unroll
    for (int q = 0; q < 8; q++) mo[tid + 256 * q] = v1[q] * invs;
}

extern "C" void kernel_launch(void* const* d_in, const int* in_sizes, int n_in,
                              void* d_out, int out_size)
{
    (void)in_sizes; (void)n_in; (void)out_size;
    const float* x       = (const float*)d_in[0];
    const float* theta_w = (const float*)d_in[1];
    const float* theta_b = (const float*)d_in[2];
    const float* phi_w   = (const float*)d_in[3];
    const float* phi_b   = (const float*)d_in[4];
    const float* g_w     = (const float*)d_in[5];
    const float* g_b     = (const float*)d_in[6];
    const float* rou_w   = (const float*)d_in[7];
    const float* rou_b   = (const float*)d_in[8];
    const float* w_w     = (const float*)d_in[9];
    const float* w_b     = (const float*)d_in[10];
    const float* emb_w   = (const float*)d_in[11];
    const float* emb_b   = (const float*)d_in[12];
    float* out = (float*)d_out;

    float *Fp, *F, *c, *P, *S1, *S2, *Mo, *Yb;
    cudaGetSymbolAddress((void**)&Fp, d_Fp);
    cudaGetSymbolAddress((void**)&F,  d_F);
    cudaGetSymbolAddress((void**)&c,  d_c);
    cudaGetSymbolAddress((void**)&P,  d_P);
    cudaGetSymbolAddress((void**)&S1, d_S1);
    cudaGetSymbolAddress((void**)&S2, d_S2);
    cudaGetSymbolAddress((void**)&Mo, d_Mo);
    cudaGetSymbolAddress((void**)&Yb, d_Yb);

    const long sBT = (long)TSQ * CIN;          // per-batch stride in x
    const long sP  = (long)TSQ * 3 * CHID;     // per-batch stride in P
    const long sTT = (long)TSQ * TSQ;

    // F = emb_w @ w_w (split-K partials, then deterministic reduce)
    gemm128<false, true, false, false, true>
        <<<dim3(CHID / 128, CEMB / 128, NKS), 256>>>(
            emb_w, w_w, Fp, nullptr,
            CEMB, CHID, CIN, CIN, CHID, CHID,
            0, 0, (long)CEMB * CHID, CIN / NKS);
    reduceF_kernel<<<(CEMB * CHID) / 256, 256>>>(Fp, F);
    cvec_kernel<<<CEMB, 256>>>(emb_w, w_b, emb_b, c);

    // projections: P = X @ W^T + b   (theta | phi | g)
    gemm128<false, false, true, false, false>
        <<<dim3(CHID / 128, (NB * TSQ) / 128, 1), 256>>>(
            x, theta_w, P, theta_b,
            NB * TSQ, CHID, CIN, CIN, CIN, 3 * CHID, 0, 0, 0, 0);
    gemm128<false, false, true, false, false>
        <<<dim3(CHID / 128, (NB * TSQ) / 128, 1), 256>>>(
            x, phi_w, P + CHID, phi_b,
            NB * TSQ, CHID, CIN, CIN, CIN, 3 * CHID, 0, 0, 0, 0);
    gemm128<false, false, true, false, false>
        <<<dim3(CHID / 128, (NB * TSQ) / 128, 1), 256>>>(
            x, g_w, P + 2 * CHID, g_b,
            NB * TSQ, CHID, CIN, CIN, CIN, 3 * CHID, 0, 0, 0, 0);

    // S1[b] = x[b] @ x[b]^T
    gemm128<false, false, false, false, false>
        <<<dim3(TSQ / 128, TSQ / 128, NB), 256>>>(
            x, x, S1, nullptr,
            TSQ, TSQ, CIN, CIN, CIN, TSQ,
            sBT, sBT, sTT, 0);

    // S2[b] = phi[b] @ theta[b]^T
    gemm128<false, false, false, false, false>
        <<<dim3(TSQ / 128, TSQ / 128, NB), 256>>>(
            P + CHID, P, S2, nullptr,
            TSQ, TSQ, CHID, 3 * CHID, 3 * CHID, TSQ,
            sP, sP, sTT, 0);

    // moca rows
    moca_kernel<<<NB * TSQ, 256>>>(S1, S2, Mo, rou_w, rou_b);

    // Y[b][s,h] = sum_t Mo[b][t,s] * g[b][t,h]   (TN)
    gemm128<true, true, false, false, false>
        <<<dim3(CHID / 128, TSQ / 128, NB), 256>>>(
            Mo, P + 2 * CHID, Yb, nullptr,
            TSQ, CHID, TSQ, TSQ, 3 * CHID, CHID,
            sTT, sP, (long)TSQ * CHID, 0);

    // out = Y @ F^T + c
    gemm128<false, false, true, false, false>
        <<<dim3(CEMB / 128, (NB * TSQ) / 128, 1), 256>>>(
            Yb, F, out, c,
            NB * TSQ, CEMB, CHID, CHID, CHID, CEMB, 0, 0, 0, 0);

    // out += X @ emb_w^T
    gemm128<false, false, false, true, false>
        <<<dim3(CEMB / 128, (NB * TSQ) / 128, 1), 256>>>(
            x, emb_w, out, nullptr,
            NB * TSQ, CEMB, CIN, CIN, CIN, CEMB, 0, 0, 0, 0);
}

// round 3
// speedup vs baseline: 2.7558x; 2.7558x over previous
#include <cuda_runtime.h>
#include <cstdint>

// ---------------------------------------------------------------------------
// MOCA_80075370266907 — tf32 tensor-core GEMM chain (mma.sync.m16n8k8).
//
//   P = X @ [theta_w|phi_w|g_w]^T + bias          (8192 x 3072)
//   S1[b] = x[b] @ x[b]^T                          (4 x 2048 x 2048)
//   S2[b] = phi[b] @ theta[b]^T
//   moca[b] = softmax(r0*softmax(rowA)+r1*softmax(rowB)+rb)   (cat quirk)
//   Y[b][s,h] = sum_t moca[b][t,s] * g[b][t,h]
//   out = Y @ F^T + X @ emb_w^T + c,  F = emb_w @ w_w (fp32 split-K)
// ---------------------------------------------------------------------------

namespace {
constexpr int CIN  = 2048;
constexpr int CHID = 1024;
constexpr int CEMB = 256;
constexpr int NB   = 4;
constexpr int TSQ  = 2048;
constexpr int NKS  = 16;

constexpr int BM = 128, BN = 128, BK = 32, STAGES = 3;
}

// scratch (static device arrays — no dynamic allocation anywhere)
__device__ float d_Fp[(size_t)NKS * CEMB * CHID];
__device__ float d_F [(size_t)CEMB * CHID];
__device__ float d_c [CEMB];
__device__ float d_P [(size_t)NB * TSQ * 3 * CHID];
__device__ float d_S1[(size_t)NB * TSQ * TSQ];
__device__ float d_S2[(size_t)NB * TSQ * TSQ];
__device__ float d_Mo[(size_t)NB * TSQ * TSQ];
__device__ float d_Yb[(size_t)NB * TSQ * CHID];

// ---------------------------------------------------------------------------
// PTX helpers
// ---------------------------------------------------------------------------
__device__ __forceinline__ uint32_t cvta_s(const void* p) {
    return (uint32_t)__cvta_generic_to_shared(p);
}
__device__ __forceinline__ void cpasync16(uint32_t dst, const void* src) {
    asm volatile("cp.async.cg.shared.global [%0], [%1], 16;\n" :: "r"(dst), "l"(src));
}
__device__ __forceinline__ void cp_commit() {
    asm volatile("cp.async.commit_group;\n");
}
template<int N> __device__ __forceinline__ void cp_wait() {
    asm volatile("cp.async.wait_group %0;\n" :: "n"(N));
}
__device__ __forceinline__ uint32_t f2tf32(float f) {
    uint32_t r;
    asm("cvt.rna.tf32.f32 %0, %1;\n" : "=r"(r) : "f"(f));
    return r;
}
__device__ __forceinline__ void mma_tf32(
    float& c0, float& c1, float& c2, float& c3,
    uint32_t a0, uint32_t a1, uint32_t a2, uint32_t a3,
    uint32_t b0, uint32_t b1)
{
    asm volatile(
        "mma.sync.aligned.m16n8k8.row.col.f32.tf32.tf32.f32 "
        "{%0,%1,%2,%3},{%4,%5,%6,%7},{%8,%9},{%0,%1,%2,%3};\n"
        : "+f"(c0), "+f"(c1), "+f"(c2), "+f"(c3)
        : "r"(a0), "r"(a1), "r"(a2), "r"(a3), "r"(b0), "r"(b1));
}

// ---------------------------------------------------------------------------
// tf32 tensor-core GEMM: 128x128x32 tiles, 256 threads, 3-stage cp.async.
//   AKM=false: A is MxK row-major      AKM=true: A is KxM row-major
//   BKN=false: B is NxK row-major (NT) BKN=true: B is KxN row-major
// M,N multiples of 128; K multiples of 32; leading dims multiples of 4.
// ---------------------------------------------------------------------------
template<bool AKM, bool BKN, bool BIAS, bool ACCUM>
__global__ __launch_bounds__(256, 1)
void tgemm(const float* __restrict__ Ag, const float* __restrict__ Bg,
           float* __restrict__ Cg, const float* __restrict__ bias,
           int K, int lda, int ldb, int ldc,
           long bsA, long bsB, long bsC)
{
    constexpr int ALD = AKM ? (BM + 8) : (BK + 4);
    constexpr int BLD = BKN ? (BN + 8) : (BK + 4);
    constexpr int SA  = AKM ? BK * ALD : BM * ALD;   // floats per A stage
    constexpr int SB  = BKN ? BK * BLD : BN * BLD;   // floats per B stage

    extern __shared__ float sm[];

    const float* A = Ag + (long)blockIdx.z * bsA;
    const float* B = Bg + (long)blockIdx.z * bsB;
    float*       C = Cg + (long)blockIdx.z * bsC;

    const int m0 = blockIdx.y * BM, n0 = blockIdx.x * BN;
    const int tid  = threadIdx.x;
    const int warp = tid >> 5, lane = tid & 31;
    const int g = lane >> 2, tg = lane & 3;     // groupID / threadInGroup
    const int wm = warp & 1, wn = warp >> 1;    // 2 x 4 warp grid

    auto load_stage = [&](int s, int kk) {
        float* As = sm + s * (SA + SB);
        float* Bs = As + SA;
        #pragma unroll
        for (int q = 0; q < 4; q++) {
            int c = tid + 256 * q;
            if (!AKM) {
                int row = c >> 3, kc = (c & 7) * 4;
                cpasync16(cvta_s(As + row * ALD + kc),
                          A + (long)(m0 + row) * lda + kk + kc);
            } else {
                int row = c >> 5, mc = (c & 31) * 4;
                cpasync16(cvta_s(As + row * ALD + mc),
                          A + (long)(kk + row) * lda + m0 + mc);
            }
        }
        #pragma unroll
        for (int q = 0; q < 4; q++) {
            int c = tid + 256 * q;
            if (!BKN) {
                int row = c >> 3, kc = (c & 7) * 4;
                cpasync16(cvta_s(Bs + row * BLD + kc),
                          B + (long)(n0 + row) * ldb + kk + kc);
            } else {
                int row = c >> 5, nc = (c & 31) * 4;
                cpasync16(cvta_s(Bs + row * BLD + nc),
                          B + (long)(kk + row) * ldb + n0 + nc);
            }
        }
        cp_commit();
    };

    float acc[4][4][4];
    #pragma unroll
    for (int i = 0; i < 4; i++)
        #pragma unroll
        for (int j = 0; j < 4; j++)
            #pragma unroll
            for (int r = 0; r < 4; r++) acc[i][j][r] = 0.f;

    const int niter = K / BK;
    load_stage(0, 0);
    load_stage(1, BK);

    for (int it = 0; it < niter; ++it) {
        cp_wait<STAGES - 2>();
        __syncthreads();
        if (it + STAGES - 1 < niter)
            load_stage((it + STAGES - 1) % STAGES, (it + STAGES - 1) * BK);

        const float* As = sm + (it % STAGES) * (SA + SB);
        const float* Bs = As + SA;

        #pragma unroll
        for (int ks = 0; ks < BK / 8; ++ks) {
            const int k = ks * 8;
            uint32_t af[4][4], bf[4][2];
            #pragma unroll
            for (int i = 0; i < 4; i++) {
                const int m = wm * 64 + i * 16 + g;
                if (!AKM) {
                    const float* p = As + m * ALD + k + tg;
                    af[i][0] = f2tf32(p[0]);
                    af[i][1] = f2tf32(p[8 * ALD]);
                    af[i][2] = f2tf32(p[4]);
                    af[i][3] = f2tf32(p[8 * ALD + 4]);
                } else {
                    const float* p = As + (k + tg) * ALD + m;
                    af[i][0] = f2tf32(p[0]);
                    af[i][1] = f2tf32(p[8]);
                    af[i][2] = f2tf32(p[4 * ALD]);
                    af[i][3] = f2tf32(p[4 * ALD + 8]);
                }
            }
            #pragma unroll
            for (int j = 0; j < 4; j++) {
                const int n = wn * 32 + j * 8 + g;
                if (!BKN) {
                    const float* p = Bs + n * BLD + k + tg;
                    bf[j][0] = f2tf32(p[0]);
                    bf[j][1] = f2tf32(p[4]);
                } else {
                    const float* p = Bs + (k + tg) * BLD + n;
                    bf[j][0] = f2tf32(p[0]);
                    bf[j][1] = f2tf32(p[4 * BLD]);
                }
            }
            #pragma unroll
            for (int i = 0; i < 4; i++)
                #pragma unroll
                for (int j = 0; j < 4; j++)
                    mma_tf32(acc[i][j][0], acc[i][j][1], acc[i][j][2], acc[i][j][3],
                             af[i][0], af[i][1], af[i][2], af[i][3],
                             bf[j][0], bf[j][1]);
        }
    }

    // epilogue: c0:(g, 2tg) c1:(g, 2tg+1) c2:(g+8, 2tg) c3:(g+8, 2tg+1)
    #pragma unroll
    for (int i = 0; i < 4; i++) {
        #pragma unroll
        for (int j = 0; j < 4; j++) {
            const int r0 = m0 + wm * 64 + i * 16 + g;
            const int cc = n0 + wn * 32 + j * 8 + tg * 2;
            float2 v0 = make_float2(acc[i][j][0], acc[i][j][1]);
            float2 v1 = make_float2(acc[i][j][2], acc[i][j][3]);
            if (BIAS) {
                float2 bb = *(const float2*)&bias[cc];
                v0.x += bb.x; v0.y += bb.y; v1.x += bb.x; v1.y += bb.y;
            }
            long o0 = (long)r0 * ldc + cc;
            long o1 = (long)(r0 + 8) * ldc + cc;
            if (ACCUM) {
                float2 t0 = *(const float2*)&C[o0];
                float2 t1 = *(const float2*)&C[o1];
                v0.x += t0.x; v0.y += t0.y; v1.x += t1.x; v1.y += t1.y;
            }
            *(float2*)&C[o0] = v0;
            *(float2*)&C[o1] = v1;
        }
    }
}

// ---------------------------------------------------------------------------
// fp32 128x128x8 SGEMM (kept only for the small split-K F gemm)
// ---------------------------------------------------------------------------
template<bool AKM, bool BKN, bool BIAS, bool ACCUM, bool SPLITK>
__global__ __launch_bounds__(256, 2)
void gemm128(const float* __restrict__ Ag, const float* __restrict__ Bg,
             float* __restrict__ Cg, const float* __restrict__ bias,
             int M, int N, int K, int lda, int ldb, int ldc,
             long sA, long sB, long sC, int ksplit)
{
    __shared__ float As[8][132];
    __shared__ float Bs[8][132];
    const float* A = Ag;
    const float* B = Bg;
    float* C = Cg;
    int kbeg = 0, kend = K;
    if (SPLITK) {
        kbeg = blockIdx.z * ksplit;
        kend = kbeg + ksplit; if (kend > K) kend = K;
        C += (long)blockIdx.z * sC;
    } else {
        A += (long)blockIdx.z * sA;
        B += (long)blockIdx.z * sB;
        C += (long)blockIdx.z * sC;
    }
    const int m0 = blockIdx.y * 128, n0 = blockIdx.x * 128;
    const int tid = threadIdx.x;
    const int tx = tid & 15, ty = tid >> 4;
    const int aRow = tid >> 1, aK4 = (tid & 1) * 4;
    const int aKr  = tid >> 5, aCol = (tid & 31) * 4;

    float acc[8][8];
    #pragma unroll
    for (int i = 0; i < 8; i++)
        #pragma unroll
        for (int j = 0; j < 8; j++) acc[i][j] = 0.f;

    for (int kk = kbeg; kk < kend; kk += 8) {
        __syncthreads();
        if (!AKM) {
            float4 v = *(const float4*)&A[(long)(m0 + aRow) * lda + kk + aK4];
            As[aK4+0][aRow] = v.x; As[aK4+1][aRow] = v.y;
            As[aK4+2][aRow] = v.z; As[aK4+3][aRow] = v.w;
        } else {
            float4 v = *(const float4*)&A[(long)(kk + aKr) * lda + m0 + aCol];
            *(float4*)&As[aKr][aCol] = v;
        }
        if (!BKN) {
            float4 v = *(const float4*)&B[(long)(n0 + aRow) * ldb + kk + aK4];
            Bs[aK4+0][aRow] = v.x; Bs[aK4+1][aRow] = v.y;
            Bs[aK4+2][aRow] = v.z; Bs[aK4+3][aRow] = v.w;
        } else {
            float4 v = *(const float4*)&B[(long)(kk + aKr) * ldb + n0 + aCol];
            *(float4*)&Bs[aKr][aCol] = v;
        }
        __syncthreads();
        #pragma unroll
        for (int k = 0; k < 8; k++) {
            float a[8], b[8];
            *(float4*)(a)     = *(const float4*)&As[k][ty * 4];
            *(float4*)(a + 4) = *(const float4*)&As[k][64 + ty * 4];
            *(float4*)(b)     = *(const float4*)&Bs[k][tx * 4];
            *(float4*)(b + 4) = *(const float4*)&Bs[k][64 + tx * 4];
            #pragma unroll
            for (int i = 0; i < 8; i++)
                #pragma unroll
                for (int j = 0; j < 8; j++)
                    acc[i][j] = fmaf(a[i], b[j], acc[i][j]);
        }
    }

    #pragma unroll
    for (int i = 0; i < 8; i++) {
        int m = m0 + ((i < 4) ? (ty * 4 + i) : (64 + ty * 4 + i - 4));
        #pragma unroll
        for (int h = 0; h < 2; h++) {
            int n = n0 + h * 64 + tx * 4;
            float4 v;
            v.x = acc[i][h*4+0]; v.y = acc[i][h*4+1];
            v.z = acc[i][h*4+2]; v.w = acc[i][h*4+3];
            long off = (long)m * ldc + n;
            if (BIAS) {
                v.x += bias[n+0]; v.y += bias[n+1];
                v.z += bias[n+2]; v.w += bias[n+3];
            }
            if (ACCUM) {
                float4 o = *(const float4*)&C[off];
                v.x += o.x; v.y += o.y; v.z += o.z; v.w += o.w;
            }
            *(float4*)&C[off] = v;
        }
    }
}

__global__ void reduceF_kernel(const float* __restrict__ Fp, float* __restrict__ F)
{
    int i = blockIdx.x * 256 + threadIdx.x;
    float s = 0.f;
    #pragma unroll
    for (int z = 0; z < NKS; z++) s += Fp[(long)z * CEMB * CHID + i];
    F[i] = s;
}

__global__ void cvec_kernel(const float* __restrict__ emb_w,
                            const float* __restrict__ w_b,
                            const float* __restrict__ emb_b,
                            float* __restrict__ c)
{
    __shared__ float red[8];
    int e = blockIdx.x;
    float s = 0.f;
    for (int o = threadIdx.x; o < CIN; o += 256)
        s += w_b[o] * emb_w[(long)e * CIN + o];
    #pragma unroll
    for (int off = 16; off; off >>= 1) s += __shfl_xor_sync(0xffffffffu, s, off);
    if ((threadIdx.x & 31) == 0) red[threadIdx.x >> 5] = s;
    __syncthreads();
    if (threadIdx.x == 0) {
        float t = 0.f;
        #pragma unroll
        for (int w = 0; w < 8; w++) t += red[w];
        c[e] = t + emb_b[e];
    }
}

__device__ __forceinline__ float warpRed(float v, bool mx)
{
    #pragma unroll
    for (int o = 16; o; o >>= 1) {
        float w = __shfl_xor_sync(0xffffffffu, v, o);
        v = mx ? fmaxf(v, w) : v + w;
    }
    return v;
}

__global__ void moca_kernel(const float* __restrict__ S1,
                            const float* __restrict__ S2,
                            float* __restrict__ Mo,
                            const float* __restrict__ rou_w,
                            const float* __restrict__ rou_b)
{
    __shared__ float red[8];
    const int row = blockIdx.x;
    const int b = row >> 11, t = row & (TSQ - 1);
    const float* buf = (b < 2) ? S1 : S2;
    const int ba = (b & 1) * 2;                 // cat(axis=0).reshape quirk
    const float* rA = buf + ((long)ba * TSQ + t) * TSQ;
    const float* rB = buf + ((long)(ba + 1) * TSQ + t) * TSQ;
    const int tid = threadIdx.x;

    float v1[8], v2[8];
    #pragma unroll
    for (int q = 0; q < 8; q++) {
        v1[q] = rA[tid + 256 * q];
        v2[q] = rB[tid + 256 * q];
    }

    auto bred = [&](float v, bool mx) -> float {
        v = warpRed(v, mx);
        __syncthreads();
        if ((tid & 31) == 0) red[tid >> 5] = v;
        __syncthreads();
        float r = red[0];
        #pragma unroll
        for (int w = 1; w < 8; w++) r = mx ? fmaxf(r, red[w]) : r + red[w];
        return r;
    };

    float m = -3.4e38f;
    #pragma unroll
    for (int q = 0; q < 8; q++) m = fmaxf(m, v1[q]);
    m = bred(m, true);
    float s = 0.f;
    #pragma unroll
    for (int q = 0; q < 8; q++) { v1[q] = __expf(v1[q] - m); s += v1[q]; }
    const float inv1 = 1.f / bred(s, false);

    m = -3.4e38f;
    #pragma unroll
    for (int q = 0; q < 8; q++) m = fmaxf(m, v2[q]);
    m = bred(m, true);
    s = 0.f;
    #pragma unroll
    for (int q = 0; q < 8; q++) { v2[q] = __expf(v2[q] - m); s += v2[q]; }
    const float inv2 = 1.f / bred(s, false);

    const float r0 = rou_w[0], r1 = rou_w[1], rb = rou_b[0];
    #pragma unroll
    for (int q = 0; q < 8; q++)
        v1[q] = r0 * v1[q] * inv1 + r1 * v2[q] * inv2 + rb;

    m = -3.4e38f;
    #pragma unroll
    for (int q = 0; q < 8; q++) m = fmaxf(m, v1[q]);
    m = bred(m, true);
    s = 0.f;
    #pragma unroll
    for (int q = 0; q < 8; q++) { v1[q] = __expf(v1[q] - m); s += v1[q]; }
    const float invs = 1.f / bred(s, false);

    float* mo = Mo + (long)row * TSQ;
    #pragma unroll
    for (int q = 0; q < 8; q++) mo[tid + 256 * q] = v1[q] * invs;
}

// ---------------------------------------------------------------------------
extern "C" void kernel_launch(void* const* d_in, const int* in_sizes, int n_in,
                              void* d_out, int out_size)
{
    (void)in_sizes; (void)n_in; (void)out_size;
    const float* x       = (const float*)d_in[0];
    const float* theta_w = (const float*)d_in[1];
    const float* theta_b = (const float*)d_in[2];
    const float* phi_w   = (const float*)d_in[3];
    const float* phi_b   = (const float*)d_in[4];
    const float* g_w     = (const float*)d_in[5];
    const float* g_b     = (const float*)d_in[6];
    const float* rou_w   = (const float*)d_in[7];
    const float* rou_b   = (const float*)d_in[8];
    const float* w_w     = (const float*)d_in[9];
    const float* w_b     = (const float*)d_in[10];
    const float* emb_w   = (const float*)d_in[11];
    const float* emb_b   = (const float*)d_in[12];
    float* out = (float*)d_out;

    float *Fp, *F, *c, *P, *S1, *S2, *Mo, *Yb;
    cudaGetSymbolAddress((void**)&Fp, d_Fp);
    cudaGetSymbolAddress((void**)&F,  d_F);
    cudaGetSymbolAddress((void**)&c,  d_c);
    cudaGetSymbolAddress((void**)&P,  d_P);
    cudaGetSymbolAddress((void**)&S1, d_S1);
    cudaGetSymbolAddress((void**)&S2, d_S2);
    cudaGetSymbolAddress((void**)&Mo, d_Mo);
    cudaGetSymbolAddress((void**)&Yb, d_Yb);

    const long sBT = (long)TSQ * CIN;
    const long sP  = (long)TSQ * 3 * CHID;
    const long sTT = (long)TSQ * TSQ;

    // dynamic smem sizes per variant (floats -> bytes)
    auto smem_bytes = [](bool akm, bool bkn) -> int {
        int sa = akm ? BK * (BM + 8) : BM * (BK + 4);
        int sb = bkn ? BK * (BN + 8) : BN * (BK + 4);
        return STAGES * (sa + sb) * (int)sizeof(float);
    };
    const int smNN = smem_bytes(false, false);
    const int smKK = smem_bytes(true,  true);

    cudaFuncSetAttribute(tgemm<false,false,true ,false>,
                         cudaFuncAttributeMaxDynamicSharedMemorySize, smNN);
    cudaFuncSetAttribute(tgemm<false,false,false,false>,
                         cudaFuncAttributeMaxDynamicSharedMemorySize, smNN);
    cudaFuncSetAttribute(tgemm<false,false,false,true >,
                         cudaFuncAttributeMaxDynamicSharedMemorySize, smNN);
    cudaFuncSetAttribute(tgemm<true ,true ,false,false>,
                         cudaFuncAttributeMaxDynamicSharedMemorySize, smKK);

    // F = emb_w @ w_w (fp32 split-K, tiny) + c vector
    gemm128<false, true, false, false, true>
        <<<dim3(CHID / 128, CEMB / 128, NKS), 256>>>(
            emb_w, w_w, Fp, nullptr,
            CEMB, CHID, CIN, CIN, CHID, CHID,
            0, 0, (long)CEMB * CHID, CIN / NKS);
    reduceF_kernel<<<(CEMB * CHID) / 256, 256>>>(Fp, F);
    cvec_kernel<<<CEMB, 256>>>(emb_w, w_b, emb_b, c);

    // projections: P = X @ W^T + b (theta | phi | g)
    tgemm<false, false, true, false>
        <<<dim3(CHID / BN, (NB * TSQ) / BM, 1), 256, smNN>>>(
            x, theta_w, P, theta_b, CIN, CIN, CIN, 3 * CHID, 0, 0, 0);
    tgemm<false, false, true, false>
        <<<dim3(CHID / BN, (NB * TSQ) / BM, 1), 256, smNN>>>(
            x, phi_w, P + CHID, phi_b, CIN, CIN, CIN, 3 * CHID, 0, 0, 0);
    tgemm<false, false, true, false>
        <<<dim3(CHID / BN, (NB * TSQ) / BM, 1), 256, smNN>>>(
            x, g_w, P + 2 * CHID, g_b, CIN, CIN, CIN, 3 * CHID, 0, 0, 0);

    // S1[b] = x[b] @ x[b]^T
    tgemm<false, false, false, false>
        <<<dim3(TSQ / BN, TSQ / BM, NB), 256, smNN>>>(
            x, x, S1, nullptr, CIN, CIN, CIN, TSQ, sBT, sBT, sTT);

    // S2[b] = phi[b] @ theta[b]^T
    tgemm<false, false, false, false>
        <<<dim3(TSQ / BN, TSQ / BM, NB), 256, smNN>>>(
            P + CHID, P, S2, nullptr, CHID, 3 * CHID, 3 * CHID, TSQ, sP, sP, sTT);

    // moca rows
    moca_kernel<<<NB * TSQ, 256>>>(S1, S2, Mo, rou_w, rou_b);

    // Y[b][s,h] = sum_t Mo[b][t,s] * g[b][t,h]  (A: KxM, B: KxN)
    tgemm<true, true, false, false>
        <<<dim3(CHID / BN, TSQ / BM, NB), 256, smKK>>>(
            Mo, P + 2 * CHID, Yb, nullptr,
            TSQ, TSQ, 3 * CHID, CHID, sTT, sP, (long)TSQ * CHID);

    // out = Y @ F^T + c
    tgemm<false, false, true, false>
        <<<dim3(CEMB / BN, (NB * TSQ) / BM, 1), 256, smNN>>>(
            Yb, F, out, c, CHID, CHID, CHID, CEMB, 0, 0, 0);

    // out += X @ emb_w^T
    tgemm<false, false, false, true>
        <<<dim3(CEMB / BN, (NB * TSQ) / BM, 1), 256, smNN>>>(
            x, emb_w, out, nullptr, CIN, CIN, CIN, CEMB, 0, 0, 0);
}

// round 4
// speedup vs baseline: 2.8533x; 1.0354x over previous
#include <cuda_runtime.h>
#include <cstdint>

// ---------------------------------------------------------------------------
// MOCA_80075370266907 — tf32 mma.sync chain, operands pre-rounded to tf32 in
// gmem so the GEMM mainloop has ZERO converts (pure LDS + HMMA).
//   P = Xr @ [theta|phi|g]^T + bias ; S1 = Xr Xr^T ; S2 = phi theta^T
//   moca = softmax(r0*sm(rowA)+r1*sm(rowB)+rb)  (cat/reshape quirk pairing)
//   Y = moca^T g ; out = Y F^T + Xr emb^T + c ;  F = emb_w @ w_w
// ---------------------------------------------------------------------------

namespace {
constexpr int CIN  = 2048;
constexpr int CHID = 1024;
constexpr int CEMB = 256;
constexpr int NB   = 4;
constexpr int TSQ  = 2048;
constexpr int NKS  = 16;

constexpr int BM = 128, BN = 128, BK = 16, STAGES = 4;
}

// static scratch
__device__ float d_Fp [(size_t)NKS * CEMB * CHID];
__device__ float d_F  [(size_t)CEMB * CHID];
__device__ float d_c  [CEMB];
__device__ float d_P  [(size_t)NB * TSQ * 3 * CHID];
__device__ float d_S1 [(size_t)NB * TSQ * TSQ];
__device__ float d_S2 [(size_t)NB * TSQ * TSQ];
__device__ float d_Mo [(size_t)NB * TSQ * TSQ];
__device__ float d_Yb [(size_t)NB * TSQ * CHID];
__device__ float d_Xr [(size_t)NB * TSQ * CIN];
__device__ float d_Wtr[(size_t)3 * CHID * CIN];
__device__ float d_Ewr[(size_t)CEMB * CIN];

// ---------------------------------------------------------------------------
__device__ __forceinline__ uint32_t cvta_s(const void* p) {
    return (uint32_t)__cvta_generic_to_shared(p);
}
__device__ __forceinline__ void cpasync16(uint32_t dst, const void* src) {
    asm volatile("cp.async.cg.shared.global [%0], [%1], 16;\n" :: "r"(dst), "l"(src));
}
__device__ __forceinline__ void cp_commit() {
    asm volatile("cp.async.commit_group;\n");
}
template<int N> __device__ __forceinline__ void cp_wait() {
    asm volatile("cp.async.wait_group %0;\n" :: "n"(N));
}
__device__ __forceinline__ uint32_t f2tf32(float f) {
    uint32_t r;
    asm("cvt.rna.tf32.f32 %0, %1;\n" : "=r"(r) : "f"(f));
    return r;
}
__device__ __forceinline__ float rnd_tf32(float f) {
    return __uint_as_float(f2tf32(f));
}
__device__ __forceinline__ void mma_tf32(
    float& c0, float& c1, float& c2, float& c3,
    uint32_t a0, uint32_t a1, uint32_t a2, uint32_t a3,
    uint32_t b0, uint32_t b1)
{
    asm volatile(
        "mma.sync.aligned.m16n8k8.row.col.f32.tf32.tf32.f32 "
        "{%0,%1,%2,%3},{%4,%5,%6,%7},{%8,%9},{%0,%1,%2,%3};\n"
        : "+f"(c0), "+f"(c1), "+f"(c2), "+f"(c3)
        : "r"(a0), "r"(a1), "r"(a2), "r"(a3), "r"(b0), "r"(b1));
}

// round a gmem array to tf32 (vectorized, n multiple of 4)
__global__ void cvt_tf32_kernel(const float* __restrict__ in,
                                float* __restrict__ out, long n4)
{
    long i = (long)blockIdx.x * 256 + threadIdx.x;
    if (i >= n4) return;
    float4 v = ((const float4*)in)[i];
    v.x = rnd_tf32(v.x); v.y = rnd_tf32(v.y);
    v.z = rnd_tf32(v.z); v.w = rnd_tf32(v.w);
    ((float4*)out)[i] = v;
}

// ---------------------------------------------------------------------------
// tf32 tensor-core GEMM: 128x128x16 tiles, 256 threads, 4-stage cp.async,
// 2 CTAs/SM. Operands are pre-rounded tf32 bits — no converts in mainloop.
//   AKM=false: A MxK row-major   AKM=true: A KxM row-major
//   BKN=false: B NxK row-major   BKN=true: B KxN row-major
//   ROUND: round C store to tf32 (when C feeds a later GEMM)
// ---------------------------------------------------------------------------
template<bool AKM, bool BKN, bool BIAS, bool ACCUM, bool ROUND>
__global__ __launch_bounds__(256, 2)
void tgemm(const float* __restrict__ Ag, const float* __restrict__ Bg,
           float* __restrict__ Cg, const float* __restrict__ bias,
           int K, int lda, int ldb, int ldc,
           long bsA, long bsB, long bsC)
{
    constexpr int ALD = AKM ? (BM + 8) : (BK + 4);
    constexpr int BLD = BKN ? (BN + 8) : (BK + 4);
    constexpr int SA  = AKM ? BK * ALD : BM * ALD;
    constexpr int SB  = BKN ? BK * BLD : BN * BLD;

    extern __shared__ float sm[];

    const float* A = Ag + (long)blockIdx.z * bsA;
    const float* B = Bg + (long)blockIdx.z * bsB;
    float*       C = Cg + (long)blockIdx.z * bsC;

    const int m0 = blockIdx.y * BM, n0 = blockIdx.x * BN;
    const int tid  = threadIdx.x;
    const int warp = tid >> 5, lane = tid & 31;
    const int g = lane >> 2, tg = lane & 3;
    const int wm = warp & 1, wn = warp >> 1;   // 2 x 4 warp grid

    auto load_stage = [&](int s, int kk) {
        float* As = sm + s * (SA + SB);
        float* Bs = As + SA;
        #pragma unroll
        for (int q = 0; q < 2; q++) {
            int c = tid + 256 * q;
            if (!AKM) {
                int row = c >> 2, kc = (c & 3) * 4;
                cpasync16(cvta_s(As + row * ALD + kc),
                          A + (long)(m0 + row) * lda + kk + kc);
            } else {
                int row = c >> 5, mc = (c & 31) * 4;
                cpasync16(cvta_s(As + row * ALD + mc),
                          A + (long)(kk + row) * lda + m0 + mc);
            }
        }
        #pragma unroll
        for (int q = 0; q < 2; q++) {
            int c = tid + 256 * q;
            if (!BKN) {
                int row = c >> 2, kc = (c & 3) * 4;
                cpasync16(cvta_s(Bs + row * BLD + kc),
                          B + (long)(n0 + row) * ldb + kk + kc);
            } else {
                int row = c >> 5, nc = (c & 31) * 4;
                cpasync16(cvta_s(Bs + row * BLD + nc),
                          B + (long)(kk + row) * ldb + n0 + nc);
            }
        }
        cp_commit();
    };

    float acc[4][4][4];
    #pragma unroll
    for (int i = 0; i < 4; i++)
        #pragma unroll
        for (int j = 0; j < 4; j++)
            #pragma unroll
            for (int r = 0; r < 4; r++) acc[i][j][r] = 0.f;

    const int niter = K / BK;
    #pragma unroll
    for (int s = 0; s < STAGES - 1; s++) load_stage(s, s * BK);

    for (int it = 0; it < niter; ++it) {
        cp_wait<STAGES - 2>();
        __syncthreads();
        if (it + STAGES - 1 < niter)
            load_stage((it + STAGES - 1) % STAGES, (it + STAGES - 1) * BK);

        const uint32_t* As = (const uint32_t*)(sm + (it % STAGES) * (SA + SB));
        const uint32_t* Bs = As + SA;

        #pragma unroll
        for (int ks = 0; ks < BK / 8; ++ks) {
            const int k = ks * 8;
            uint32_t af[4][4], bf[4][2];
            #pragma unroll
            for (int i = 0; i < 4; i++) {
                const int m = wm * 64 + i * 16 + g;
                if (!AKM) {
                    const uint32_t* p = As + m * ALD + k + tg;
                    af[i][0] = p[0];
                    af[i][1] = p[8 * ALD];
                    af[i][2] = p[4];
                    af[i][3] = p[8 * ALD + 4];
                } else {
                    const uint32_t* p = As + (k + tg) * ALD + m;
                    af[i][0] = p[0];
                    af[i][1] = p[8];
                    af[i][2] = p[4 * ALD];
                    af[i][3] = p[4 * ALD + 8];
                }
            }
            #pragma unroll
            for (int j = 0; j < 4; j++) {
                const int n = wn * 32 + j * 8 + g;
                if (!BKN) {
                    const uint32_t* p = Bs + n * BLD + k + tg;
                    bf[j][0] = p[0];
                    bf[j][1] = p[4];
                } else {
                    const uint32_t* p = Bs + (k + tg) * BLD + n;
                    bf[j][0] = p[0];
                    bf[j][1] = p[4 * BLD];
                }
            }
            #pragma unroll
            for (int i = 0; i < 4; i++)
                #pragma unroll
                for (int j = 0; j < 4; j++)
                    mma_tf32(acc[i][j][0], acc[i][j][1], acc[i][j][2], acc[i][j][3],
                             af[i][0], af[i][1], af[i][2], af[i][3],
                             bf[j][0], bf[j][1]);
        }
    }

    #pragma unroll
    for (int i = 0; i < 4; i++) {
        #pragma unroll
        for (int j = 0; j < 4; j++) {
            const int r0 = m0 + wm * 64 + i * 16 + g;
            const int cc = n0 + wn * 32 + j * 8 + tg * 2;
            float2 v0 = make_float2(acc[i][j][0], acc[i][j][1]);
            float2 v1 = make_float2(acc[i][j][2], acc[i][j][3]);
            if (BIAS) {
                float2 bb = *(const float2*)&bias[cc];
                v0.x += bb.x; v0.y += bb.y; v1.x += bb.x; v1.y += bb.y;
            }
            long o0 = (long)r0 * ldc + cc;
            long o1 = (long)(r0 + 8) * ldc + cc;
            if (ACCUM) {
                float2 t0 = *(const float2*)&C[o0];
                float2 t1 = *(const float2*)&C[o1];
                v0.x += t0.x; v0.y += t0.y; v1.x += t1.x; v1.y += t1.y;
            }
            if (ROUND) {
                v0.x = rnd_tf32(v0.x); v0.y = rnd_tf32(v0.y);
                v1.x = rnd_tf32(v1.x); v1.y = rnd_tf32(v1.y);
            }
            *(float2*)&C[o0] = v0;
            *(float2*)&C[o1] = v1;
        }
    }
}

// ---------------------------------------------------------------------------
// fp32 128x128x8 SGEMM (only for small split-K F gemm)
// ---------------------------------------------------------------------------
template<bool BKN, bool SPLITK>
__global__ __launch_bounds__(256, 2)
void gemm128(const float* __restrict__ Ag, const float* __restrict__ Bg,
             float* __restrict__ Cg,
             int M, int N, int K, int lda, int ldb, int ldc,
             long sC, int ksplit)
{
    __shared__ float As[8][132];
    __shared__ float Bs[8][132];
    const float* A = Ag;
    const float* B = Bg;
    float* C = Cg;
    int kbeg = 0, kend = K;
    if (SPLITK) {
        kbeg = blockIdx.z * ksplit;
        kend = kbeg + ksplit; if (kend > K) kend = K;
        C += (long)blockIdx.z * sC;
    }
    const int m0 = blockIdx.y * 128, n0 = blockIdx.x * 128;
    const int tid = threadIdx.x;
    const int tx = tid & 15, ty = tid >> 4;
    const int aRow = tid >> 1, aK4 = (tid & 1) * 4;
    const int aKr  = tid >> 5, aCol = (tid & 31) * 4;

    float acc[8][8];
    #pragma unroll
    for (int i = 0; i < 8; i++)
        #pragma unroll
        for (int j = 0; j < 8; j++) acc[i][j] = 0.f;

    for (int kk = kbeg; kk < kend; kk += 8) {
        __syncthreads();
        {
            float4 v = *(const float4*)&A[(long)(m0 + aRow) * lda + kk + aK4];
            As[aK4+0][aRow] = v.x; As[aK4+1][aRow] = v.y;
            As[aK4+2][aRow] = v.z; As[aK4+3][aRow] = v.w;
        }
        if (!BKN) {
            float4 v = *(const float4*)&B[(long)(n0 + aRow) * ldb + kk + aK4];
            Bs[aK4+0][aRow] = v.x; Bs[aK4+1][aRow] = v.y;
            Bs[aK4+2][aRow] = v.z; Bs[aK4+3][aRow] = v.w;
        } else {
            float4 v = *(const float4*)&B[(long)(kk + aKr) * ldb + n0 + aCol];
            *(float4*)&Bs[aKr][aCol] = v;
        }
        __syncthreads();
        #pragma unroll
        for (int k = 0; k < 8; k++) {
            float a[8], b[8];
            *(float4*)(a)     = *(const float4*)&As[k][ty * 4];
            *(float4*)(a + 4) = *(const float4*)&As[k][64 + ty * 4];
            *(float4*)(b)     = *(const float4*)&Bs[k][tx * 4];
            *(float4*)(b + 4) = *(const float4*)&Bs[k][64 + tx * 4];
            #pragma unroll
            for (int i = 0; i < 8; i++)
                #pragma unroll
                for (int j = 0; j < 8; j++)
                    acc[i][j] = fmaf(a[i], b[j], acc[i][j]);
        }
    }

    #pragma unroll
    for (int i = 0; i < 8; i++) {
        int m = m0 + ((i < 4) ? (ty * 4 + i) : (64 + ty * 4 + i - 4));
        #pragma unroll
        for (int h = 0; h < 2; h++) {
            int n = n0 + h * 64 + tx * 4;
            float4 v;
            v.x = acc[i][h*4+0]; v.y = acc[i][h*4+1];
            v.z = acc[i][h*4+2]; v.w = acc[i][h*4+3];
            *(float4*)&C[(long)m * ldc + n] = v;
        }
    }
}

__global__ void reduceF_kernel(const float* __restrict__ Fp, float* __restrict__ F)
{
    int i = blockIdx.x * 256 + threadIdx.x;
    float s = 0.f;
    #pragma unroll
    for (int z = 0; z < NKS; z++) s += Fp[(long)z * CEMB * CHID + i];
    F[i] = rnd_tf32(s);
}

__global__ void cvec_kernel(const float* __restrict__ emb_w,
                            const float* __restrict__ w_b,
                            const float* __restrict__ emb_b,
                            float* __restrict__ c)
{
    __shared__ float red[8];
    int e = blockIdx.x;
    float s = 0.f;
    for (int o = threadIdx.x; o < CIN; o += 256)
        s += w_b[o] * emb_w[(long)e * CIN + o];
    #pragma unroll
    for (int off = 16; off; off >>= 1) s += __shfl_xor_sync(0xffffffffu, s, off);
    if ((threadIdx.x & 31) == 0) red[threadIdx.x >> 5] = s;
    __syncthreads();
    if (threadIdx.x == 0) {
        float t = 0.f;
        #pragma unroll
        for (int w = 0; w < 8; w++) t += red[w];
        c[e] = t + emb_b[e];
    }
}

__device__ __forceinline__ float warpRed(float v, bool mx)
{
    #pragma unroll
    for (int o = 16; o; o >>= 1) {
        float w = __shfl_xor_sync(0xffffffffu, v, o);
        v = mx ? fmaxf(v, w) : v + w;
    }
    return v;
}

__global__ void moca_kernel(const float* __restrict__ S1,
                            const float* __restrict__ S2,
                            float* __restrict__ Mo,
                            const float* __restrict__ rou_w,
                            const float* __restrict__ rou_b)
{
    __shared__ float red[8];
    const int row = blockIdx.x;
    const int b = row >> 11, t = row & (TSQ - 1);
    const float* buf = (b < 2) ? S1 : S2;
    const int ba = (b & 1) * 2;                 // cat(axis=0).reshape quirk
    const float* rA = buf + ((long)ba * TSQ + t) * TSQ;
    const float* rB = buf + ((long)(ba + 1) * TSQ + t) * TSQ;
    const int tid = threadIdx.x;

    float v1[8], v2[8];
    #pragma unroll
    for (int q = 0; q < 8; q++) {
        v1[q] = rA[tid + 256 * q];
        v2[q] = rB[tid + 256 * q];
    }

    auto bred = [&](float v, bool mx) -> float {
        v = warpRed(v, mx);
        __syncthreads();
        if ((tid & 31) == 0) red[tid >> 5] = v;
        __syncthreads();
        float r = red[0];
        #pragma unroll
        for (int w = 1; w < 8; w++) r = mx ? fmaxf(r, red[w]) : r + red[w];
        return r;
    };

    float m = -3.4e38f;
    #pragma unroll
    for (int q = 0; q < 8; q++) m = fmaxf(m, v1[q]);
    m = bred(m, true);
    float s = 0.f;
    #pragma unroll
    for (int q = 0; q < 8; q++) { v1[q] = __expf(v1[q] - m); s += v1[q]; }
    const float inv1 = 1.f / bred(s, false);

    m = -3.4e38f;
    #pragma unroll
    for (int q = 0; q < 8; q++) m = fmaxf(m, v2[q]);
    m = bred(m, true);
    s = 0.f;
    #pragma unroll
    for (int q = 0; q < 8; q++) { v2[q] = __expf(v2[q] - m); s += v2[q]; }
    const float inv2 = 1.f / bred(s, false);

    const float r0 = rou_w[0], r1 = rou_w[1], rb = rou_b[0];
    #pragma unroll
    for (int q = 0; q < 8; q++)
        v1[q] = r0 * v1[q] * inv1 + r1 * v2[q] * inv2 + rb;

    m = -3.4e38f;
    #pragma unroll
    for (int q = 0; q < 8; q++) m = fmaxf(m, v1[q]);
    m = bred(m, true);
    s = 0.f;
    #pragma unroll
    for (int q = 0; q < 8; q++) { v1[q] = __expf(v1[q] - m); s += v1[q]; }
    const float invs = 1.f / bred(s, false);

    float* mo = Mo + (long)row * TSQ;
    #pragma unroll
    for (int q = 0; q < 8; q++) mo[tid + 256 * q] = rnd_tf32(v1[q] * invs);
}

// ---------------------------------------------------------------------------
extern "C" void kernel_launch(void* const* d_in, const int* in_sizes, int n_in,
                              void* d_out, int out_size)
{
    (void)in_sizes; (void)n_in; (void)out_size;
    const float* x       = (const float*)d_in[0];
    const float* theta_w = (const float*)d_in[1];
    const float* theta_b = (const float*)d_in[2];
    const float* phi_w   = (const float*)d_in[3];
    const float* phi_b   = (const float*)d_in[4];
    const float* g_w     = (const float*)d_in[5];
    const float* g_b     = (const float*)d_in[6];
    const float* rou_w   = (const float*)d_in[7];
    const float* rou_b   = (const float*)d_in[8];
    const float* w_w     = (const float*)d_in[9];
    const float* w_b     = (const float*)d_in[10];
    const float* emb_w   = (const float*)d_in[11];
    const float* emb_b   = (const float*)d_in[12];
    float* out = (float*)d_out;

    float *Fp, *F, *c, *P, *S1, *S2, *Mo, *Yb, *Xr, *Wtr, *Ewr;
    cudaGetSymbolAddress((void**)&Fp,  d_Fp);
    cudaGetSymbolAddress((void**)&F,   d_F);
    cudaGetSymbolAddress((void**)&c,   d_c);
    cudaGetSymbolAddress((void**)&P,   d_P);
    cudaGetSymbolAddress((void**)&S1,  d_S1);
    cudaGetSymbolAddress((void**)&S2,  d_S2);
    cudaGetSymbolAddress((void**)&Mo,  d_Mo);
    cudaGetSymbolAddress((void**)&Yb,  d_Yb);
    cudaGetSymbolAddress((void**)&Xr,  d_Xr);
    cudaGetSymbolAddress((void**)&Wtr, d_Wtr);
    cudaGetSymbolAddress((void**)&Ewr, d_Ewr);

    const long sBT = (long)TSQ * CIN;
    const long sP  = (long)TSQ * 3 * CHID;
    const long sTT = (long)TSQ * TSQ;

    auto smem_bytes = [](bool akm, bool bkn) -> int {
        int sa = akm ? BK * (BM + 8) : BM * (BK + 4);
        int sb = bkn ? BK * (BN + 8) : BN * (BK + 4);
        return STAGES * (sa + sb) * (int)sizeof(float);
    };
    const int smNN = smem_bytes(false, false);
    const int smKK = smem_bytes(true,  true);

    cudaFuncSetAttribute(tgemm<false,false,true ,false,true >,
                         cudaFuncAttributeMaxDynamicSharedMemorySize, smNN);
    cudaFuncSetAttribute(tgemm<false,false,false,false,false>,
                         cudaFuncAttributeMaxDynamicSharedMemorySize, smNN);
    cudaFuncSetAttribute(tgemm<false,false,true ,false,false>,
                         cudaFuncAttributeMaxDynamicSharedMemorySize, smNN);
    cudaFuncSetAttribute(tgemm<false,false,false,true ,false>,
                         cudaFuncAttributeMaxDynamicSharedMemorySize, smNN);
    cudaFuncSetAttribute(tgemm<true ,true ,false,false,true >,
                         cudaFuncAttributeMaxDynamicSharedMemorySize, smKK);

    // pre-round operands to tf32 in gmem
    const long nx4 = (long)NB * TSQ * CIN / 4;
    cvt_tf32_kernel<<<(int)((nx4 + 255) / 256), 256>>>(x, Xr, nx4);
    const long nw4 = (long)CHID * CIN / 4;
    cvt_tf32_kernel<<<(int)((nw4 + 255) / 256), 256>>>(theta_w, Wtr, nw4);
    cvt_tf32_kernel<<<(int)((nw4 + 255) / 256), 256>>>(phi_w,  Wtr + (long)CHID * CIN, nw4);
    cvt_tf32_kernel<<<(int)((nw4 + 255) / 256), 256>>>(g_w,    Wtr + 2L * CHID * CIN, nw4);
    const long ne4 = (long)CEMB * CIN / 4;
    cvt_tf32_kernel<<<(int)((ne4 + 255) / 256), 256>>>(emb_w, Ewr, ne4);

    // F = emb_w @ w_w (fp32 split-K) -> rounded ; c vector
    gemm128<true, true>
        <<<dim3(CHID / 128, CEMB / 128, NKS), 256>>>(
            emb_w, w_w, Fp,
            CEMB, CHID, CIN, CIN, CHID, CHID,
            (long)CEMB * CHID, CIN / NKS);
    reduceF_kernel<<<(CEMB * CHID) / 256, 256>>>(Fp, F);
    cvec_kernel<<<CEMB, 256>>>(emb_w, w_b, emb_b, c);

    // projections: P = Xr @ W^T + b (rounded output)
    tgemm<false, false, true, false, true>
        <<<dim3(CHID / BN, (NB * TSQ) / BM, 1), 256, smNN>>>(
            Xr, Wtr, P, theta_b, CIN, CIN, CIN, 3 * CHID, 0, 0, 0);
    tgemm<false, false, true, false, true>
        <<<dim3(CHID / BN, (NB * TSQ) / BM, 1), 256, smNN>>>(
            Xr, Wtr + (long)CHID * CIN, P + CHID, phi_b, CIN, CIN, CIN, 3 * CHID, 0, 0, 0);
    tgemm<false, false, true, false, true>
        <<<dim3(CHID / BN, (NB * TSQ) / BM, 1), 256, smNN>>>(
            Xr, Wtr + 2L * CHID * CIN, P + 2 * CHID, g_b, CIN, CIN, CIN, 3 * CHID, 0, 0, 0);

    // S1[b] = Xr[b] @ Xr[b]^T
    tgemm<false, false, false, false, false>
        <<<dim3(TSQ / BN, TSQ / BM, NB), 256, smNN>>>(
            Xr, Xr, S1, nullptr, CIN, CIN, CIN, TSQ, sBT, sBT, sTT);

    // S2[b] = phi[b] @ theta[b]^T
    tgemm<false, false, false, false, false>
        <<<dim3(TSQ / BN, TSQ / BM, NB), 256, smNN>>>(
            P + CHID, P, S2, nullptr, CHID, 3 * CHID, 3 * CHID, TSQ, sP, sP, sTT);

    // moca rows (rounded output)
    moca_kernel<<<NB * TSQ, 256>>>(S1, S2, Mo, rou_w, rou_b);

    // Y[b][s,h] = sum_t Mo[b][t,s] * g[b][t,h]  (A: KxM, B: KxN, rounded out)
    tgemm<true, true, false, false, true>
        <<<dim3(CHID / BN, TSQ / BM, NB), 256, smKK>>>(
            Mo, P + 2 * CHID, Yb, nullptr,
            TSQ, TSQ, 3 * CHID, CHID, sTT, sP, (long)TSQ * CHID);

    // out = Yb @ F^T + c
    tgemm<false, false, true, false, false>
        <<<dim3(CEMB / BN, (NB * TSQ) / BM, 1), 256, smNN>>>(
            Yb, F, out, c, CHID, CHID, CHID, CEMB, 0, 0, 0);

    // out += Xr @ emb_w^T
    tgemm<false, false, false, true, false>
        <<<dim3(CEMB / BN, (NB * TSQ) / BM, 1), 256, smNN>>>(
            Xr, Ewr, out, nullptr, CIN, CIN, CIN, CEMB, 0, 0, 0);
}